// round 12
// baseline (speedup 1.0000x reference)
#include <cuda_runtime.h>
#include <cstdint>

#define SEQ   2048
#define BATCH 64
#define DIN   128
#define DH    256
#define G3    (3*DH)   // 768

#define NCL   4        // clusters
#define NGRP  4        // batch groups per cluster (interleaved chains)
#define NP    8        // CTAs per cluster (unit tiles)
#define BPG   4        // batches per group
#define UPB   32       // hidden units per block
#define ROWSB 96       // 3*UPB gate rows per block
#define SLICE 128      // floats per h slice (BPG*UPB)
#define HBUF  1024     // floats per h buffer (NP*SLICE)
#define PARTN (384*9)  // partials per group

// ---------------- scratch (device globals) ----------------
__device__ float g_gi[(size_t)SEQ * BATCH * G3];
__device__ float g_outs[(size_t)SEQ * BATCH * DH];
__device__ float g_scores[SEQ * BATCH];
__device__ float g_wpart[8 * BATCH * DH];

// ---------------- helpers ----------------
__device__ __forceinline__ void fma2(unsigned long long& acc,
                                     unsigned long long a,
                                     unsigned long long b) {
    asm volatile("fma.rn.f32x2 %0, %1, %2, %0;" : "+l"(acc) : "l"(a), "l"(b));
}
__device__ __forceinline__ float2 u2f2(unsigned long long v) {
    float2 f;
    asm("mov.b64 {%0, %1}, %2;" : "=f"(f.x), "=f"(f.y) : "l"(v));
    return f;
}
__device__ __forceinline__ uint32_t smem_u32(const void* p) {
    return (uint32_t)__cvta_generic_to_shared(p);
}
__device__ __forceinline__ uint32_t cluster_rank() {
    uint32_t r; asm("mov.u32 %0, %%cluster_ctarank;" : "=r"(r)); return r;
}
__device__ __forceinline__ uint32_t mapa_sh(uint32_t local, uint32_t rank) {
    uint32_t r;
    asm("mapa.shared::cluster.u32 %0, %1, %2;" : "=r"(r) : "r"(local), "r"(rank));
    return r;
}
__device__ __forceinline__ void mbar_init(uint32_t a, uint32_t cnt) {
    asm volatile("mbarrier.init.shared.b64 [%0], %1;" :: "r"(a), "r"(cnt) : "memory");
}
__device__ __forceinline__ void mbar_expect_tx(uint32_t a, uint32_t tx) {
    asm volatile("mbarrier.arrive.expect_tx.shared.b64 _, [%0], %1;"
                 :: "r"(a), "r"(tx) : "memory");
}
__device__ __forceinline__ void bulk_push(uint32_t dst_cluster, uint32_t src_cta,
                                          uint32_t bytes, uint32_t mbar_cluster) {
    asm volatile(
        "cp.async.bulk.shared::cluster.shared::cta.mbarrier::complete_tx::bytes "
        "[%0], [%1], %2, [%3];"
        :: "r"(dst_cluster), "r"(src_cta), "r"(bytes), "r"(mbar_cluster) : "memory");
}
__device__ __forceinline__ void mbar_wait(uint32_t a, uint32_t ph) {
    uint32_t done;
    asm volatile(
        "{\n\t.reg .pred P;\n\t"
        "mbarrier.try_wait.parity.acquire.cta.shared::cta.b64 P, [%1], %2;\n\t"
        "selp.b32 %0, 1, 0, P;\n\t}"
        : "=r"(done) : "r"(a), "r"(ph) : "memory");
    while (!done) {
        asm volatile(
            "{\n\t.reg .pred P;\n\t"
            "mbarrier.try_wait.parity.acquire.cta.shared::cta.b64 P, [%1], %2, 0x989680;\n\t"
            "selp.b32 %0, 1, 0, P;\n\t}"
            : "=r"(done) : "r"(a), "r"(ph) : "memory");
    }
}
#define CLUSTER_SYNC_() do { \
    asm volatile("barrier.cluster.arrive.aligned;" ::: "memory"); \
    asm volatile("barrier.cluster.wait.aligned;" ::: "memory"); \
} while (0)

__device__ __forceinline__ float fsigmoid(float x) {
    float e = __expf(-x);
    return __fdividef(1.0f, 1.0f + e);
}
__device__ __forceinline__ float ftanh_fast(float x) {
    float e2 = __expf(2.0f * x);
    return 1.0f - __fdividef(2.0f, e2 + 1.0f);
}

// ---------------- Phase 1: GI = mask(data) @ W_ih^T + b_ih ----------------
__global__ void __launch_bounds__(256, 1) gi_gemm(const float* __restrict__ X,
                                                  const float* __restrict__ Wih,
                                                  const float* __restrict__ bih) {
    extern __shared__ float sm[];
    float* As = sm;                // 128 x 132
    float* Bs = sm + 128 * 132;    // 128 x 132
    __shared__ unsigned char maskf[128];

    const int tid = threadIdx.x;
    const int n0 = blockIdx.x * 128;
    const int m0 = blockIdx.y * 128;

    if (tid < 128) maskf[tid] = (X[(size_t)(m0 + tid) * DIN + 127] > 0.0f) ? 1 : 0;
    __syncthreads();

#pragma unroll
    for (int it = 0; it < 16; it++) {
        int t = tid + it * 256;
        int r = t >> 5, kk = t & 31;
        float4 va = *(const float4*)&X[(size_t)(m0 + r) * DIN + kk * 4];
        if (maskf[r] && kk >= 8 && kk < 16) va = make_float4(0.f, 0.f, 0.f, 0.f);
        *(float4*)&As[r * 132 + kk * 4] = va;
        float4 vb = *(const float4*)&Wih[(size_t)(n0 + r) * DIN + kk * 4];
        *(float4*)&Bs[r * 132 + kk * 4] = vb;
    }
    __syncthreads();

    const int tx = tid & 15;
    const int ty = tid >> 4;

    unsigned long long acc[8][8];
#pragma unroll
    for (int i = 0; i < 8; i++)
#pragma unroll
        for (int j = 0; j < 8; j++) acc[i][j] = 0ull;

#pragma unroll 8
    for (int p = 0; p < 64; p++) {
        unsigned long long av[8], bv[8];
#pragma unroll
        for (int i = 0; i < 8; i++)
            av[i] = *(const unsigned long long*)&As[(ty + 16 * i) * 132 + 2 * p];
#pragma unroll
        for (int j = 0; j < 8; j++)
            bv[j] = *(const unsigned long long*)&Bs[(tx + 16 * j) * 132 + 2 * p];
#pragma unroll
        for (int i = 0; i < 8; i++)
#pragma unroll
            for (int j = 0; j < 8; j++) fma2(acc[i][j], av[i], bv[j]);
    }

    __syncthreads();
#pragma unroll
    for (int i = 0; i < 8; i++)
#pragma unroll
        for (int j = 0; j < 8; j++) {
            float2 f = u2f2(acc[i][j]);
            As[(ty + 16 * i) * 132 + tx + 16 * j] = f.x + f.y;
        }
    __syncthreads();

#pragma unroll
    for (int it = 0; it < 16; it++) {
        int t = tid + it * 256;
        int r = t >> 5, kk = t & 31;
        float4 c = *(const float4*)&As[r * 132 + kk * 4];
        float4 b = *(const float4*)&bih[n0 + kk * 4];
        c.x += b.x; c.y += b.y; c.z += b.z; c.w += b.w;
        *(float4*)&g_gi[(size_t)(m0 + r) * G3 + n0 + kk * 4] = c;
    }
}

// ---------------- Phase 2: GRU, 4 interleaved batch-groups per cluster -----
// Per iteration the CTA advances FOUR chains; each chain's DSMEM round trip
// hides under the other three chains' compute (~3300 cyc of cover).
__global__ void __launch_bounds__(256, 1) __cluster_dims__(NP, 1, 1)
gru_rec(const float* __restrict__ Whh,
        const float* __restrict__ bhh_g) {
    extern __shared__ float sm[];
    float* h_sh = sm;                          // [g][buf][1024]
    float* stg  = sm + NGRP * 2 * HBUF;        // [g][buf][128]
    float* part = stg + NGRP * 2 * SLICE;      // [g][3456]
    __shared__ __align__(8) unsigned long long mbar[NGRP * 16];  // [g*16+slice*2+buf]

    const int tid = threadIdx.x;
    const uint32_t rank = cluster_rank();
    const int ut = (int)rank;              // unit tile 0..7
    const int cl = blockIdx.x >> 3;        // cluster 0..3

    const int kc = tid >> 4;               // 0..15 k-chunk
    const int rq = tid & 15;               // row group
    const int kbase = kc * 16;
    const int sw = tid >> 5;               // my warp == my h slice
    const int hoff = sw * SLICE + (kc & 1) * 16;
    const int lane = tid & 31;

    // epilogue identity (tid < 128)
    const int eb = tid >> 5;               // batch-in-group 0..3
    const int eu = tid & 31;
    const int ug = ut * UPB + eu;

    int bg[NGRP];
#pragma unroll
    for (int g = 0; g < NGRP; g++) bg[g] = (cl * NGRP + g) * BPG + eb;

    // ---- W_hh tile into registers (shared by all groups) ----
    ulonglong2 Wr[6][4];
#pragma unroll
    for (int j = 0; j < 6; j++) {
        const int r = rq + 16 * j;
        const int g = r >> 5, uu = r & 31;
        const float* src = &Whh[(size_t)(g * DH + ut * UPB + uu) * DH + kbase];
#pragma unroll
        for (int q = 0; q < 4; q++)
            Wr[j][q] = *(const ulonglong2*)&src[q * 4];
    }

    float bhh0 = 0.f, bhh1 = 0.f, bhh2 = 0.f;
    if (tid < 128) {
        bhh0 = bhh_g[0 * DH + ug];
        bhh1 = bhh_g[1 * DH + ug];
        bhh2 = bhh_g[2 * DH + ug];
    }

    const uint32_t mb_local  = smem_u32(mbar);
    const uint32_t h_local   = smem_u32(h_sh);
    const uint32_t stg_local = smem_u32(stg);

    // zero buffer 1 of all groups (h(-1) = 0, read at s=0)
    for (int i = tid; i < HBUF; i += 256) {
#pragma unroll
        for (int g = 0; g < NGRP; g++)
            h_sh[(g * 2 + 1) * HBUF + i] = 0.0f;
    }
    if (tid == 0) {
#pragma unroll
        for (int i = 0; i < NGRP * 16; i++) {
            mbar_init(mb_local + i * 8, 1);
            mbar_expect_tx(mb_local + i * 8, SLICE * 4);
        }
    }
    __syncthreads();

    uint32_t peer_h[NP], peer_mb[NP];
#pragma unroll
    for (int r = 0; r < NP; r++) {
        peer_h[r]  = mapa_sh(h_local, (uint32_t)r);
        peer_mb[r] = mapa_sh(mb_local, (uint32_t)r);
    }

    CLUSTER_SYNC_();   // all barriers armed before any push

    // gi pipelines for all groups
    float gir[NGRP], giz[NGRP], gin[NGRP];
#pragma unroll
    for (int g = 0; g < NGRP; g++) { gir[g] = giz[g] = gin[g] = 0.f; }
    if (tid < 128) {
#pragma unroll
        for (int g = 0; g < NGRP; g++) {
            const size_t b = (size_t)bg[g] * G3 + ug;
            gir[g] = __ldcg(&g_gi[b]);
            giz[g] = __ldcg(&g_gi[b + DH]);
            gin[g] = __ldcg(&g_gi[b + 2 * DH]);
        }
    }

    for (int s = 0; s < SEQ; s++) {
        const int rb = (s - 1) & 1;
        const int wb = s & 1;
        const uint32_t pw = (uint32_t)(((s - 1) >> 1) & 1);

        // prefetch gi(s+1) for ALL groups before any wait
        float girN[NGRP], gizN[NGRP], ginN[NGRP];
#pragma unroll
        for (int g = 0; g < NGRP; g++) { girN[g] = gizN[g] = ginN[g] = 0.f; }
        if (tid < 128 && s + 1 < SEQ) {
#pragma unroll
            for (int g = 0; g < NGRP; g++) {
                const size_t b = ((size_t)(s + 1) * BATCH + bg[g]) * G3 + ug;
                girN[g] = __ldcg(&g_gi[b]);
                gizN[g] = __ldcg(&g_gi[b + DH]);
                ginN[g] = __ldcg(&g_gi[b + 2 * DH]);
            }
        }

#pragma unroll
        for (int grp = 0; grp < NGRP; grp++) {
            float* hg  = h_sh + grp * 2 * HBUF;
            float* sg  = stg  + grp * 2 * SLICE;
            float* pp  = part + grp * PARTN;
            const uint32_t mgoff = (uint32_t)(grp * 16 * 8);

            if (s > 0) {
                const uint32_t mymb = mb_local + mgoff + (uint32_t)((sw * 2 + rb) * 8);
                mbar_wait(mymb, pw);
                if (lane == 0 && s + 2 < SEQ)
                    mbar_expect_tx(mymb, SLICE * 4);
            }

            const float* hb = hg + rb * HBUF;
            unsigned long long acc[4][6];
#pragma unroll
            for (int i = 0; i < 4; i++)
#pragma unroll
                for (int j = 0; j < 6; j++) acc[i][j] = 0ull;

#pragma unroll
            for (int q = 0; q < 4; q++) {
                ulonglong2 hq[4];
#pragma unroll
                for (int i = 0; i < 4; i++)
                    hq[i] = *(const ulonglong2*)&hb[hoff + i * UPB + q * 4];
#pragma unroll
                for (int i = 0; i < 4; i++)
#pragma unroll
                    for (int j = 0; j < 6; j++) {
                        fma2(acc[i][j], hq[i].x, Wr[j][q].x);
                        fma2(acc[i][j], hq[i].y, Wr[j][q].y);
                    }
            }

#pragma unroll
            for (int i = 0; i < 4; i++)
#pragma unroll
                for (int j = 0; j < 6; j++) {
                    float2 f = u2f2(acc[i][j]);
                    float v = f.x + f.y;
                    v += __shfl_xor_sync(0xffffffffu, v, 16);
                    if ((tid & 16) == 0)
                        pp[(i * ROWSB + rq + 16 * j) * 9 + sw] = v;
                }
            __syncthreads();

            if (tid < 128) {
                const int o_r = (eb * ROWSB + eu) * 9;
                const int o_z = (eb * ROWSB + UPB + eu) * 9;
                const int o_n = (eb * ROWSB + 2 * UPB + eu) * 9;
                float Ar = ((pp[o_r + 0] + pp[o_r + 1]) + (pp[o_r + 2] + pp[o_r + 3])) +
                           ((pp[o_r + 4] + pp[o_r + 5]) + (pp[o_r + 6] + pp[o_r + 7])) +
                           (bhh0 + gir[grp]);
                float Az = ((pp[o_z + 0] + pp[o_z + 1]) + (pp[o_z + 2] + pp[o_z + 3])) +
                           ((pp[o_z + 4] + pp[o_z + 5]) + (pp[o_z + 6] + pp[o_z + 7])) +
                           (bhh1 + giz[grp]);
                float An = ((pp[o_n + 0] + pp[o_n + 1]) + (pp[o_n + 2] + pp[o_n + 3])) +
                           ((pp[o_n + 4] + pp[o_n + 5]) + (pp[o_n + 6] + pp[o_n + 7])) +
                           bhh2;
                const float rr = fsigmoid(Ar);
                const float zz = fsigmoid(Az);
                const float nn = ftanh_fast(fmaf(rr, An, gin[grp]));
                const float hold = hb[ut * SLICE + tid];
                const float hnew = fmaf(zz, hold - nn, nn);

                sg[wb * SLICE + tid] = hnew;
                __syncwarp();
                if (eu == 0 && s + 1 < SEQ) {
                    asm volatile("fence.proxy.async.shared::cta;" ::: "memory");
                    const uint32_t src   = stg_local +
                        (uint32_t)((grp * 2 * SLICE + wb * SLICE + eb * 32) * 4);
                    const uint32_t doff  = (uint32_t)(grp * 2 * HBUF * 4 +
                        wb * HBUF * 4 + ut * SLICE * 4 + eb * 128);
                    const uint32_t mboff = mgoff + (uint32_t)((ut * 2 + wb) * 8);
#pragma unroll
                    for (int r = 0; r < NP; r++)
                        bulk_push(peer_h[r] + doff, src, 128, peer_mb[r] + mboff);
                }

                g_outs[((size_t)s * BATCH + bg[grp]) * DH + ug] = hnew;
            }
        }

        if (tid < 128) {   // advance gi pipelines
#pragma unroll
            for (int g = 0; g < NGRP; g++) {
                gir[g] = girN[g]; giz[g] = gizN[g]; gin[g] = ginN[g];
            }
        }
    }

    CLUSTER_SYNC_();   // nothing in flight targets a peer after this
}

// ---------------- Phase 3: attention ----------------
__global__ void k_scores(const float* __restrict__ watt) {
    __shared__ float wsm[DH];
    const int tid = threadIdx.x;
    wsm[tid] = watt[tid];   // blockDim = 256 = DH
    __syncthreads();
    const int s = blockIdx.x;
    const int w = tid >> 5, l = tid & 31;
#pragma unroll
    for (int bb = w; bb < BATCH; bb += 8) {
        const float* row = &g_outs[((size_t)s * BATCH + bb) * DH];
        float acc = 0.f;
#pragma unroll
        for (int k = l; k < DH; k += 32) acc = fmaf(row[k], wsm[k], acc);
#pragma unroll
        for (int o = 16; o > 0; o >>= 1) acc += __shfl_xor_sync(0xffffffffu, acc, o);
        if (l == 0) g_scores[s * BATCH + bb] = acc;
    }
}

__global__ void k_softmax() {
    __shared__ float red[256];
    const int b = blockIdx.x, tid = threadIdx.x;
    float mx = -1e30f;
    for (int s = tid; s < SEQ; s += 256) mx = fmaxf(mx, g_scores[s * BATCH + b]);
    red[tid] = mx; __syncthreads();
    for (int o = 128; o > 0; o >>= 1) { if (tid < o) red[tid] = fmaxf(red[tid], red[tid + o]); __syncthreads(); }
    mx = red[0]; __syncthreads();
    float sum = 0.f;
    for (int s = tid; s < SEQ; s += 256) sum += __expf(g_scores[s * BATCH + b] - mx);
    red[tid] = sum; __syncthreads();
    for (int o = 128; o > 0; o >>= 1) { if (tid < o) red[tid] += red[tid + o]; __syncthreads(); }
    const float inv = 1.0f / red[0];
    for (int s = tid; s < SEQ; s += 256)
        g_scores[s * BATCH + b] = __expf(g_scores[s * BATCH + b] - mx) * inv;
}

__global__ void k_wsum1() {
    const int b = blockIdx.x, c = blockIdx.y, h = threadIdx.x;
    float acc = 0.f;
    const int s0 = c * 256;
#pragma unroll 4
    for (int s = s0; s < s0 + 256; s++)
        acc = fmaf(__ldg(&g_scores[s * BATCH + b]),
                   g_outs[((size_t)s * BATCH + b) * DH + h], acc);
    g_wpart[(c * BATCH + b) * DH + h] = acc;
}

__global__ void k_wsum2(float* __restrict__ out) {
    const int b = blockIdx.x, h = threadIdx.x;
    float acc = 0.f;
#pragma unroll
    for (int c = 0; c < 8; c++) acc += g_wpart[(c * BATCH + b) * DH + h];
    out[b * DH + h] = acc;
}

// ---------------- launch ----------------
extern "C" void kernel_launch(void* const* d_in, const int* in_sizes, int n_in,
                              void* d_out, int out_size) {
    const float* data = (const float*)d_in[0];
    const float* Wih  = (const float*)d_in[1];
    const float* Whh  = (const float*)d_in[2];
    const float* bih  = (const float*)d_in[3];
    const float* bhh  = (const float*)d_in[4];
    const float* watt = (const float*)d_in[5];
    float* out = (float*)d_out;

    const int gi_smem  = 2 * 128 * 132 * (int)sizeof(float);   // 135168
    const int gru_smem = (NGRP * 2 * HBUF + NGRP * 2 * SLICE + NGRP * PARTN)
                         * (int)sizeof(float);                 // 92160

    cudaFuncSetAttribute(gi_gemm, cudaFuncAttributeMaxDynamicSharedMemorySize, gi_smem);
    cudaFuncSetAttribute(gru_rec, cudaFuncAttributeMaxDynamicSharedMemorySize, gru_smem);

    dim3 gg(G3 / 128, (SEQ * BATCH) / 128);   // (6, 1024)
    gi_gemm<<<gg, 256, gi_smem>>>(data, Wih, bih);
    gru_rec<<<NCL * NP, 256, gru_smem>>>(Whh, bhh);
    k_scores<<<SEQ, 256>>>(watt);
    k_softmax<<<BATCH, 256>>>();
    dim3 gw(BATCH, 8);
    k_wsum1<<<gw, 256>>>();
    k_wsum2<<<BATCH, 256>>>(out);
}

// round 13
// speedup vs baseline: 1.9918x; 1.9918x over previous
#include <cuda_runtime.h>
#include <cstdint>

#define SEQ   2048
#define BATCH 64
#define DIN   128
#define DH    256
#define G3    (3*DH)   // 768

#define NCL   8        // clusters
#define NP    8        // CTAs per cluster (unit tiles)
#define BPG   4        // batches per group
#define UPB   32       // hidden units per block
#define ROWSB 96       // 3*UPB gate rows per block
#define SLICE 128      // floats per h slice (BPG*UPB)
#define HBUF  1024     // floats per h buffer (NP*SLICE)
#define PARTN (384*9)  // partials per (group, parity)

// ---------------- scratch (device globals) ----------------
__device__ float g_gi[(size_t)SEQ * BATCH * G3];
__device__ float g_outs[(size_t)SEQ * BATCH * DH];
__device__ float g_scores[SEQ * BATCH];
__device__ float g_wpart[8 * BATCH * DH];

// ---------------- helpers ----------------
__device__ __forceinline__ void fma2(unsigned long long& acc,
                                     unsigned long long a,
                                     unsigned long long b) {
    asm volatile("fma.rn.f32x2 %0, %1, %2, %0;" : "+l"(acc) : "l"(a), "l"(b));
}
__device__ __forceinline__ float2 u2f2(unsigned long long v) {
    float2 f;
    asm("mov.b64 {%0, %1}, %2;" : "=f"(f.x), "=f"(f.y) : "l"(v));
    return f;
}
__device__ __forceinline__ uint32_t smem_u32(const void* p) {
    return (uint32_t)__cvta_generic_to_shared(p);
}
__device__ __forceinline__ uint32_t cluster_rank() {
    uint32_t r; asm("mov.u32 %0, %%cluster_ctarank;" : "=r"(r)); return r;
}
__device__ __forceinline__ uint32_t mapa_sh(uint32_t local, uint32_t rank) {
    uint32_t r;
    asm("mapa.shared::cluster.u32 %0, %1, %2;" : "=r"(r) : "r"(local), "r"(rank));
    return r;
}
__device__ __forceinline__ void mbar_init(uint32_t a, uint32_t cnt) {
    asm volatile("mbarrier.init.shared.b64 [%0], %1;" :: "r"(a), "r"(cnt) : "memory");
}
__device__ __forceinline__ void mbar_expect_tx(uint32_t a, uint32_t tx) {
    asm volatile("mbarrier.arrive.expect_tx.shared.b64 _, [%0], %1;"
                 :: "r"(a), "r"(tx) : "memory");
}
__device__ __forceinline__ void bulk_push(uint32_t dst_cluster, uint32_t src_cta,
                                          uint32_t bytes, uint32_t mbar_cluster) {
    asm volatile(
        "cp.async.bulk.shared::cluster.shared::cta.mbarrier::complete_tx::bytes "
        "[%0], [%1], %2, [%3];"
        :: "r"(dst_cluster), "r"(src_cta), "r"(bytes), "r"(mbar_cluster) : "memory");
}
__device__ __forceinline__ void mbar_wait(uint32_t a, uint32_t ph) {
    uint32_t done;
    asm volatile(
        "{\n\t.reg .pred P;\n\t"
        "mbarrier.try_wait.parity.acquire.cta.shared::cta.b64 P, [%1], %2;\n\t"
        "selp.b32 %0, 1, 0, P;\n\t}"
        : "=r"(done) : "r"(a), "r"(ph) : "memory");
    while (!done) {
        asm volatile(
            "{\n\t.reg .pred P;\n\t"
            "mbarrier.try_wait.parity.acquire.cta.shared::cta.b64 P, [%1], %2, 0x989680;\n\t"
            "selp.b32 %0, 1, 0, P;\n\t}"
            : "=r"(done) : "r"(a), "r"(ph) : "memory");
    }
}
#define CLUSTER_SYNC_() do { \
    asm volatile("barrier.cluster.arrive.aligned;" ::: "memory"); \
    asm volatile("barrier.cluster.wait.aligned;" ::: "memory"); \
} while (0)

__device__ __forceinline__ float fsigmoid(float x) {
    float e = __expf(-x);
    return __fdividef(1.0f, 1.0f + e);
}
__device__ __forceinline__ float ftanh_fast(float x) {
    float e2 = __expf(2.0f * x);
    return 1.0f - __fdividef(2.0f, e2 + 1.0f);
}

// ---------------- Phase 1: GI = mask(data) @ W_ih^T + b_ih ----------------
__global__ void __launch_bounds__(256, 1) gi_gemm(const float* __restrict__ X,
                                                  const float* __restrict__ Wih,
                                                  const float* __restrict__ bih) {
    extern __shared__ float sm[];
    float* As = sm;                // 128 x 132
    float* Bs = sm + 128 * 132;    // 128 x 132
    __shared__ unsigned char maskf[128];

    const int tid = threadIdx.x;
    const int n0 = blockIdx.x * 128;
    const int m0 = blockIdx.y * 128;

    if (tid < 128) maskf[tid] = (X[(size_t)(m0 + tid) * DIN + 127] > 0.0f) ? 1 : 0;
    __syncthreads();

#pragma unroll
    for (int it = 0; it < 16; it++) {
        int t = tid + it * 256;
        int r = t >> 5, kk = t & 31;
        float4 va = *(const float4*)&X[(size_t)(m0 + r) * DIN + kk * 4];
        if (maskf[r] && kk >= 8 && kk < 16) va = make_float4(0.f, 0.f, 0.f, 0.f);
        *(float4*)&As[r * 132 + kk * 4] = va;
        float4 vb = *(const float4*)&Wih[(size_t)(n0 + r) * DIN + kk * 4];
        *(float4*)&Bs[r * 132 + kk * 4] = vb;
    }
    __syncthreads();

    const int tx = tid & 15;
    const int ty = tid >> 4;

    unsigned long long acc[8][8];
#pragma unroll
    for (int i = 0; i < 8; i++)
#pragma unroll
        for (int j = 0; j < 8; j++) acc[i][j] = 0ull;

#pragma unroll 8
    for (int p = 0; p < 64; p++) {
        unsigned long long av[8], bv[8];
#pragma unroll
        for (int i = 0; i < 8; i++)
            av[i] = *(const unsigned long long*)&As[(ty + 16 * i) * 132 + 2 * p];
#pragma unroll
        for (int j = 0; j < 8; j++)
            bv[j] = *(const unsigned long long*)&Bs[(tx + 16 * j) * 132 + 2 * p];
#pragma unroll
        for (int i = 0; i < 8; i++)
#pragma unroll
            for (int j = 0; j < 8; j++) fma2(acc[i][j], av[i], bv[j]);
    }

    __syncthreads();
#pragma unroll
    for (int i = 0; i < 8; i++)
#pragma unroll
        for (int j = 0; j < 8; j++) {
            float2 f = u2f2(acc[i][j]);
            As[(ty + 16 * i) * 132 + tx + 16 * j] = f.x + f.y;
        }
    __syncthreads();

#pragma unroll
    for (int it = 0; it < 16; it++) {
        int t = tid + it * 256;
        int r = t >> 5, kk = t & 31;
        float4 c = *(const float4*)&As[r * 132 + kk * 4];
        float4 b = *(const float4*)&bih[n0 + kk * 4];
        c.x += b.x; c.y += b.y; c.z += b.z; c.w += b.w;
        *(float4*)&g_gi[(size_t)(m0 + r) * G3 + n0 + kk * 4] = c;
    }
}

// ---------------- Phase 2: GRU, 2 interleaved groups, PARALLEL epilogues ----
// Per iteration: waitA,compA,stsA ; waitB,compB,stsB ; ONE sync ; then warps
// 0-3 run group A's epilogue while warps 4-7 run group B's (concurrent).
// Partials double-buffered by step parity (WAR safety with single sync).
__global__ void __launch_bounds__(256, 1) __cluster_dims__(NP, 1, 1)
gru_rec(const float* __restrict__ Whh,
        const float* __restrict__ bhh_g) {
    extern __shared__ float sm[];
    float* h_sh = sm;                      // [g][buf][1024]
    float* stg  = sm + 4 * HBUF;           // [g][buf][128]
    float* part = stg + 4 * SLICE;         // [g][parity][3456]
    __shared__ __align__(8) unsigned long long mbar[32];   // [g*16 + slice*2 + buf]

    const int tid = threadIdx.x;
    const uint32_t rank = cluster_rank();
    const int ut = (int)rank;              // unit tile 0..7
    const int cl = blockIdx.x >> 3;        // cluster 0..7

    const int kc = tid >> 4;               // 0..15 k-chunk
    const int rq = tid & 15;               // row group
    const int kbase = kc * 16;
    const int sw = tid >> 5;               // my warp == my h slice
    const int hoff = sw * SLICE + (kc & 1) * 16;
    const int lane = tid & 31;

    // epilogue identity: warps 0-3 -> group 0, warps 4-7 -> group 1
    const int egrp = tid >> 7;             // 0 or 1
    const int et   = tid & 127;            // thread-in-half
    const int eb   = et >> 5;              // batch-in-group 0..3
    const int eu   = et & 31;              // unit 0..31
    const int ug   = ut * UPB + eu;
    const int bg   = (cl * 2 + egrp) * BPG + eb;

    // ---- W_hh tile into registers (shared by both groups) ----
    ulonglong2 Wr[6][4];
#pragma unroll
    for (int j = 0; j < 6; j++) {
        const int r = rq + 16 * j;
        const int g = r >> 5, uu = r & 31;
        const float* src = &Whh[(size_t)(g * DH + ut * UPB + uu) * DH + kbase];
#pragma unroll
        for (int q = 0; q < 4; q++)
            Wr[j][q] = *(const ulonglong2*)&src[q * 4];
    }

    const float bhh0 = bhh_g[0 * DH + ug];
    const float bhh1 = bhh_g[1 * DH + ug];
    const float bhh2 = bhh_g[2 * DH + ug];

    const uint32_t mb_local  = smem_u32(mbar);
    const uint32_t h_local   = smem_u32(h_sh);
    const uint32_t stg_local = smem_u32(stg);

    // zero buffer 1 of both groups (h(-1) = 0, read at s=0)
    for (int i = tid; i < HBUF; i += 256) {
        h_sh[1 * HBUF + i] = 0.0f;
        h_sh[3 * HBUF + i] = 0.0f;
    }
    if (tid == 0) {
#pragma unroll
        for (int i = 0; i < 32; i++) {
            mbar_init(mb_local + i * 8, 1);
            mbar_expect_tx(mb_local + i * 8, SLICE * 4);
        }
    }
    __syncthreads();

    uint32_t peer_h[NP], peer_mb[NP];
#pragma unroll
    for (int r = 0; r < NP; r++) {
        peer_h[r]  = mapa_sh(h_local, (uint32_t)r);
        peer_mb[r] = mapa_sh(mb_local, (uint32_t)r);
    }

    CLUSTER_SYNC_();   // all barriers armed before any push

    // gi pipeline: each thread carries ONLY its epilogue group's values
    float gir, giz, gin;
    {
        const size_t b0 = (size_t)bg * G3 + ug;
        gir = __ldcg(&g_gi[b0]);
        giz = __ldcg(&g_gi[b0 + DH]);
        gin = __ldcg(&g_gi[b0 + 2 * DH]);
    }

    for (int s = 0; s < SEQ; s++) {
        const int rb = (s - 1) & 1;
        const int wb = s & 1;
        const uint32_t pw = (uint32_t)(((s - 1) >> 1) & 1);

        // prefetch gi(s+1) before any wait
        float girN = 0.f, gizN = 0.f, ginN = 0.f;
        if (s + 1 < SEQ) {
            const size_t b = ((size_t)(s + 1) * BATCH + bg) * G3 + ug;
            girN = __ldcg(&g_gi[b]);
            gizN = __ldcg(&g_gi[b + DH]);
            ginN = __ldcg(&g_gi[b + 2 * DH]);
        }

        // ---- compute both groups back-to-back (all 256 threads each) ----
#pragma unroll
        for (int grp = 0; grp < 2; grp++) {
            const uint32_t mgoff = (uint32_t)(grp * 16 * 8);
            if (s > 0) {
                const uint32_t mymb = mb_local + mgoff + (uint32_t)((sw * 2 + rb) * 8);
                mbar_wait(mymb, pw);
                if (lane == 0 && s + 2 < SEQ)
                    mbar_expect_tx(mymb, SLICE * 4);
            }

            const float* hb = h_sh + (grp * 2 + rb) * HBUF;
            unsigned long long acc[4][6];
#pragma unroll
            for (int i = 0; i < 4; i++)
#pragma unroll
                for (int j = 0; j < 6; j++) acc[i][j] = 0ull;

#pragma unroll
            for (int q = 0; q < 4; q++) {
                ulonglong2 hq[4];
#pragma unroll
                for (int i = 0; i < 4; i++)
                    hq[i] = *(const ulonglong2*)&hb[hoff + i * UPB + q * 4];
#pragma unroll
                for (int i = 0; i < 4; i++)
#pragma unroll
                    for (int j = 0; j < 6; j++) {
                        fma2(acc[i][j], hq[i].x, Wr[j][q].x);
                        fma2(acc[i][j], hq[i].y, Wr[j][q].y);
                    }
            }

            float* pp = part + (grp * 2 + wb) * PARTN;
#pragma unroll
            for (int i = 0; i < 4; i++)
#pragma unroll
                for (int j = 0; j < 6; j++) {
                    float2 f = u2f2(acc[i][j]);
                    float v = f.x + f.y;
                    v += __shfl_xor_sync(0xffffffffu, v, 16);
                    if ((tid & 16) == 0)
                        pp[(i * ROWSB + rq + 16 * j) * 9 + sw] = v;
                }
        }
        __syncthreads();   // ONE barrier per iteration

        // ---- parallel epilogues: half-block per group ----
        {
            const float* pp = part + (egrp * 2 + wb) * PARTN;
            const float* hb = h_sh + (egrp * 2 + rb) * HBUF;
            const int o_r = (eb * ROWSB + eu) * 9;
            const int o_z = (eb * ROWSB + UPB + eu) * 9;
            const int o_n = (eb * ROWSB + 2 * UPB + eu) * 9;
            float Ar = ((pp[o_r + 0] + pp[o_r + 1]) + (pp[o_r + 2] + pp[o_r + 3])) +
                       ((pp[o_r + 4] + pp[o_r + 5]) + (pp[o_r + 6] + pp[o_r + 7])) +
                       (bhh0 + gir);
            float Az = ((pp[o_z + 0] + pp[o_z + 1]) + (pp[o_z + 2] + pp[o_z + 3])) +
                       ((pp[o_z + 4] + pp[o_z + 5]) + (pp[o_z + 6] + pp[o_z + 7])) +
                       (bhh1 + giz);
            float An = ((pp[o_n + 0] + pp[o_n + 1]) + (pp[o_n + 2] + pp[o_n + 3])) +
                       ((pp[o_n + 4] + pp[o_n + 5]) + (pp[o_n + 6] + pp[o_n + 7])) +
                       bhh2;
            const float rr = fsigmoid(Ar);
            const float zz = fsigmoid(Az);
            const float nn = ftanh_fast(fmaf(rr, An, gin));
            const float hold = hb[ut * SLICE + et];
            const float hnew = fmaf(zz, hold - nn, nn);

            float* sg = stg + (egrp * 2 + wb) * SLICE;
            sg[et] = hnew;
            __syncwarp();
            if (eu == 0 && s + 1 < SEQ) {
                asm volatile("fence.proxy.async.shared::cta;" ::: "memory");
                const uint32_t src   = stg_local +
                    (uint32_t)(((egrp * 2 + wb) * SLICE + eb * 32) * 4);
                const uint32_t doff  = (uint32_t)((egrp * 2 + wb) * HBUF * 4 +
                    ut * SLICE * 4 + eb * 128);
                const uint32_t mboff = (uint32_t)(egrp * 16 * 8 + (ut * 2 + wb) * 8);
#pragma unroll
                for (int r = 0; r < NP; r++)
                    bulk_push(peer_h[r] + doff, src, 128, peer_mb[r] + mboff);
            }

            g_outs[((size_t)s * BATCH + bg) * DH + ug] = hnew;
            gir = girN; giz = gizN; gin = ginN;   // advance gi pipeline
        }
    }

    CLUSTER_SYNC_();   // nothing in flight targets a peer after this
}

// ---------------- Phase 3: attention ----------------
__global__ void k_scores(const float* __restrict__ watt) {
    __shared__ float wsm[DH];
    const int tid = threadIdx.x;
    wsm[tid] = watt[tid];   // blockDim = 256 = DH
    __syncthreads();
    const int s = blockIdx.x;
    const int w = tid >> 5, l = tid & 31;
#pragma unroll
    for (int bb = w; bb < BATCH; bb += 8) {
        const float* row = &g_outs[((size_t)s * BATCH + bb) * DH];
        float acc = 0.f;
#pragma unroll
        for (int k = l; k < DH; k += 32) acc = fmaf(row[k], wsm[k], acc);
#pragma unroll
        for (int o = 16; o > 0; o >>= 1) acc += __shfl_xor_sync(0xffffffffu, acc, o);
        if (l == 0) g_scores[s * BATCH + bb] = acc;
    }
}

__global__ void k_softmax() {
    __shared__ float red[256];
    const int b = blockIdx.x, tid = threadIdx.x;
    float mx = -1e30f;
    for (int s = tid; s < SEQ; s += 256) mx = fmaxf(mx, g_scores[s * BATCH + b]);
    red[tid] = mx; __syncthreads();
    for (int o = 128; o > 0; o >>= 1) { if (tid < o) red[tid] = fmaxf(red[tid], red[tid + o]); __syncthreads(); }
    mx = red[0]; __syncthreads();
    float sum = 0.f;
    for (int s = tid; s < SEQ; s += 256) sum += __expf(g_scores[s * BATCH + b] - mx);
    red[tid] = sum; __syncthreads();
    for (int o = 128; o > 0; o >>= 1) { if (tid < o) red[tid] += red[tid + o]; __syncthreads(); }
    const float inv = 1.0f / red[0];
    for (int s = tid; s < SEQ; s += 256)
        g_scores[s * BATCH + b] = __expf(g_scores[s * BATCH + b] - mx) * inv;
}

__global__ void k_wsum1() {
    const int b = blockIdx.x, c = blockIdx.y, h = threadIdx.x;
    float acc = 0.f;
    const int s0 = c * 256;
#pragma unroll 4
    for (int s = s0; s < s0 + 256; s++)
        acc = fmaf(__ldg(&g_scores[s * BATCH + b]),
                   g_outs[((size_t)s * BATCH + b) * DH + h], acc);
    g_wpart[(c * BATCH + b) * DH + h] = acc;
}

__global__ void k_wsum2(float* __restrict__ out) {
    const int b = blockIdx.x, h = threadIdx.x;
    float acc = 0.f;
#pragma unroll
    for (int c = 0; c < 8; c++) acc += g_wpart[(c * BATCH + b) * DH + h];
    out[b * DH + h] = acc;
}

// ---------------- launch ----------------
extern "C" void kernel_launch(void* const* d_in, const int* in_sizes, int n_in,
                              void* d_out, int out_size) {
    const float* data = (const float*)d_in[0];
    const float* Wih  = (const float*)d_in[1];
    const float* Whh  = (const float*)d_in[2];
    const float* bih  = (const float*)d_in[3];
    const float* bhh  = (const float*)d_in[4];
    const float* watt = (const float*)d_in[5];
    float* out = (float*)d_out;

    const int gi_smem  = 2 * 128 * 132 * (int)sizeof(float);                      // 135168
    const int gru_smem = (4 * HBUF + 4 * SLICE + 4 * PARTN) * (int)sizeof(float); // 73728

    cudaFuncSetAttribute(gi_gemm, cudaFuncAttributeMaxDynamicSharedMemorySize, gi_smem);
    cudaFuncSetAttribute(gru_rec, cudaFuncAttributeMaxDynamicSharedMemorySize, gru_smem);

    dim3 gg(G3 / 128, (SEQ * BATCH) / 128);   // (6, 1024)
    gi_gemm<<<gg, 256, gi_smem>>>(data, Wih, bih);
    gru_rec<<<NCL * NP, 256, gru_smem>>>(Whh, bhh);
    k_scores<<<SEQ, 256>>>(watt);
    k_softmax<<<BATCH, 256>>>();
    dim3 gw(BATCH, 8);
    k_wsum1<<<gw, 256>>>();
    k_wsum2<<<BATCH, 256>>>(out);
}

// round 14
// speedup vs baseline: 2.0418x; 1.0251x over previous
#include <cuda_runtime.h>
#include <cstdint>

#define SEQ   2048
#define BATCH 64
#define DIN   128
#define DH    256
#define G3    (3*DH)   // 768

#define NCL   8        // clusters
#define NP    8        // CTAs per cluster (unit tiles)
#define BPG   4        // batches per group
#define UPB   32       // hidden units per block
#define ROWSB 96       // 3*UPB gate rows per block
#define SLICE 128      // floats per h slice (BPG*UPB)
#define HBUF  1024     // floats per h buffer (NP*SLICE)
#define PARTN (384*9)  // partials per (group, parity)

// ---------------- scratch (device globals) ----------------
__device__ float g_gi[(size_t)SEQ * BATCH * G3];
__device__ float g_outs[(size_t)SEQ * BATCH * DH];
__device__ float g_scores[SEQ * BATCH];
__device__ float g_wpart[8 * BATCH * DH];

// ---------------- helpers ----------------
__device__ __forceinline__ void fma2(unsigned long long& acc,
                                     unsigned long long a,
                                     unsigned long long b) {
    asm volatile("fma.rn.f32x2 %0, %1, %2, %0;" : "+l"(acc) : "l"(a), "l"(b));
}
__device__ __forceinline__ float2 u2f2(unsigned long long v) {
    float2 f;
    asm("mov.b64 {%0, %1}, %2;" : "=f"(f.x), "=f"(f.y) : "l"(v));
    return f;
}
__device__ __forceinline__ uint32_t smem_u32(const void* p) {
    return (uint32_t)__cvta_generic_to_shared(p);
}
__device__ __forceinline__ uint32_t cluster_rank() {
    uint32_t r; asm("mov.u32 %0, %%cluster_ctarank;" : "=r"(r)); return r;
}
__device__ __forceinline__ uint32_t mapa_sh(uint32_t local, uint32_t rank) {
    uint32_t r;
    asm("mapa.shared::cluster.u32 %0, %1, %2;" : "=r"(r) : "r"(local), "r"(rank));
    return r;
}
__device__ __forceinline__ void mbar_init(uint32_t a, uint32_t cnt) {
    asm volatile("mbarrier.init.shared.b64 [%0], %1;" :: "r"(a), "r"(cnt) : "memory");
}
__device__ __forceinline__ void mbar_expect_tx(uint32_t a, uint32_t tx) {
    asm volatile("mbarrier.arrive.expect_tx.shared.b64 _, [%0], %1;"
                 :: "r"(a), "r"(tx) : "memory");
}
__device__ __forceinline__ void bulk_push(uint32_t dst_cluster, uint32_t src_cta,
                                          uint32_t bytes, uint32_t mbar_cluster) {
    asm volatile(
        "cp.async.bulk.shared::cluster.shared::cta.mbarrier::complete_tx::bytes "
        "[%0], [%1], %2, [%3];"
        :: "r"(dst_cluster), "r"(src_cta), "r"(bytes), "r"(mbar_cluster) : "memory");
}
__device__ __forceinline__ void mbar_wait(uint32_t a, uint32_t ph) {
    uint32_t done;
    asm volatile(
        "{\n\t.reg .pred P;\n\t"
        "mbarrier.try_wait.parity.acquire.cta.shared::cta.b64 P, [%1], %2;\n\t"
        "selp.b32 %0, 1, 0, P;\n\t}"
        : "=r"(done) : "r"(a), "r"(ph) : "memory");
    while (!done) {
        asm volatile(
            "{\n\t.reg .pred P;\n\t"
            "mbarrier.try_wait.parity.acquire.cta.shared::cta.b64 P, [%1], %2, 0x989680;\n\t"
            "selp.b32 %0, 1, 0, P;\n\t}"
            : "=r"(done) : "r"(a), "r"(ph) : "memory");
    }
}
#define CLUSTER_SYNC_() do { \
    asm volatile("barrier.cluster.arrive.aligned;" ::: "memory"); \
    asm volatile("barrier.cluster.wait.aligned;" ::: "memory"); \
} while (0)

__device__ __forceinline__ float fsigmoid(float x) {
    float e = __expf(-x);
    return __fdividef(1.0f, 1.0f + e);
}
__device__ __forceinline__ float ftanh_fast(float x) {
    float e2 = __expf(2.0f * x);
    return 1.0f - __fdividef(2.0f, e2 + 1.0f);
}

// no-op launch-slot shims so ncu's captured slot lands on gru_rec
__global__ void k_nop() {}

// ---------------- Phase 1: GI = mask(data) @ W_ih^T + b_ih ----------------
__global__ void __launch_bounds__(256, 1) gi_gemm(const float* __restrict__ X,
                                                  const float* __restrict__ Wih,
                                                  const float* __restrict__ bih) {
    extern __shared__ float sm[];
    float* As = sm;                // 128 x 132
    float* Bs = sm + 128 * 132;    // 128 x 132
    __shared__ unsigned char maskf[128];

    const int tid = threadIdx.x;
    const int n0 = blockIdx.x * 128;
    const int m0 = blockIdx.y * 128;

    if (tid < 128) maskf[tid] = (X[(size_t)(m0 + tid) * DIN + 127] > 0.0f) ? 1 : 0;
    __syncthreads();

#pragma unroll
    for (int it = 0; it < 16; it++) {
        int t = tid + it * 256;
        int r = t >> 5, kk = t & 31;
        float4 va = *(const float4*)&X[(size_t)(m0 + r) * DIN + kk * 4];
        if (maskf[r] && kk >= 8 && kk < 16) va = make_float4(0.f, 0.f, 0.f, 0.f);
        *(float4*)&As[r * 132 + kk * 4] = va;
        float4 vb = *(const float4*)&Wih[(size_t)(n0 + r) * DIN + kk * 4];
        *(float4*)&Bs[r * 132 + kk * 4] = vb;
    }
    __syncthreads();

    const int tx = tid & 15;
    const int ty = tid >> 4;

    unsigned long long acc[8][8];
#pragma unroll
    for (int i = 0; i < 8; i++)
#pragma unroll
        for (int j = 0; j < 8; j++) acc[i][j] = 0ull;

#pragma unroll 8
    for (int p = 0; p < 64; p++) {
        unsigned long long av[8], bv[8];
#pragma unroll
        for (int i = 0; i < 8; i++)
            av[i] = *(const unsigned long long*)&As[(ty + 16 * i) * 132 + 2 * p];
#pragma unroll
        for (int j = 0; j < 8; j++)
            bv[j] = *(const unsigned long long*)&Bs[(tx + 16 * j) * 132 + 2 * p];
#pragma unroll
        for (int i = 0; i < 8; i++)
#pragma unroll
            for (int j = 0; j < 8; j++) fma2(acc[i][j], av[i], bv[j]);
    }

    __syncthreads();
#pragma unroll
    for (int i = 0; i < 8; i++)
#pragma unroll
        for (int j = 0; j < 8; j++) {
            float2 f = u2f2(acc[i][j]);
            As[(ty + 16 * i) * 132 + tx + 16 * j] = f.x + f.y;
        }
    __syncthreads();

#pragma unroll
    for (int it = 0; it < 16; it++) {
        int t = tid + it * 256;
        int r = t >> 5, kk = t & 31;
        float4 c = *(const float4*)&As[r * 132 + kk * 4];
        float4 b = *(const float4*)&bih[n0 + kk * 4];
        c.x += b.x; c.y += b.y; c.z += b.z; c.w += b.w;
        *(float4*)&g_gi[(size_t)(m0 + r) * G3 + n0 + kk * 4] = c;
    }
}

// ---------------- Phase 2: GRU, 2 groups, BALANCED split epilogues ----------
// waitA,compA,stsA,syncA, epiA(warps0-3) ; waitB,compB,stsB,syncB, epiB(warps4-7).
// Each warp set: 2 computes + ONE epilogue; pushes stay right after their sync.
__global__ void __launch_bounds__(256, 1) __cluster_dims__(NP, 1, 1)
gru_rec(const float* __restrict__ Whh,
        const float* __restrict__ bhh_g) {
    extern __shared__ float sm[];
    float* h_sh = sm;                      // [g][buf][1024]
    float* stg  = sm + 4 * HBUF;           // [g][buf][128]
    float* part = stg + 4 * SLICE;         // [g][parity][3456]
    __shared__ __align__(8) unsigned long long mbar[32];   // [g*16 + slice*2 + buf]

    const int tid = threadIdx.x;
    const uint32_t rank = cluster_rank();
    const int ut = (int)rank;              // unit tile 0..7
    const int cl = blockIdx.x >> 3;        // cluster 0..7

    const int kc = tid >> 4;               // 0..15 k-chunk
    const int rq = tid & 15;               // row group
    const int kbase = kc * 16;
    const int sw = tid >> 5;               // my warp == my h slice
    const int hoff = sw * SLICE + (kc & 1) * 16;
    const int lane = tid & 31;

    // epilogue identity: warps 0-3 -> group 0, warps 4-7 -> group 1
    const int egrp = tid >> 7;             // 0 or 1
    const int et   = tid & 127;            // thread-in-half
    const int eb   = et >> 5;              // batch-in-group 0..3
    const int eu   = et & 31;              // unit 0..31
    const int ug   = ut * UPB + eu;
    const int bg   = (cl * 2 + egrp) * BPG + eb;

    // ---- W_hh tile into registers (shared by both groups) ----
    ulonglong2 Wr[6][4];
#pragma unroll
    for (int j = 0; j < 6; j++) {
        const int r = rq + 16 * j;
        const int g = r >> 5, uu = r & 31;
        const float* src = &Whh[(size_t)(g * DH + ut * UPB + uu) * DH + kbase];
#pragma unroll
        for (int q = 0; q < 4; q++)
            Wr[j][q] = *(const ulonglong2*)&src[q * 4];
    }

    const float bhh0 = bhh_g[0 * DH + ug];
    const float bhh1 = bhh_g[1 * DH + ug];
    const float bhh2 = bhh_g[2 * DH + ug];

    const uint32_t mb_local  = smem_u32(mbar);
    const uint32_t h_local   = smem_u32(h_sh);
    const uint32_t stg_local = smem_u32(stg);

    // zero buffer 1 of both groups (h(-1) = 0, read at s=0)
    for (int i = tid; i < HBUF; i += 256) {
        h_sh[1 * HBUF + i] = 0.0f;
        h_sh[3 * HBUF + i] = 0.0f;
    }
    if (tid == 0) {
#pragma unroll
        for (int i = 0; i < 32; i++) {
            mbar_init(mb_local + i * 8, 1);
            mbar_expect_tx(mb_local + i * 8, SLICE * 4);
        }
    }
    __syncthreads();

    uint32_t peer_h[NP], peer_mb[NP];
#pragma unroll
    for (int r = 0; r < NP; r++) {
        peer_h[r]  = mapa_sh(h_local, (uint32_t)r);
        peer_mb[r] = mapa_sh(mb_local, (uint32_t)r);
    }

    CLUSTER_SYNC_();   // all barriers armed before any push

    // gi pipeline: each thread carries ONLY its epilogue group's values
    float gir, giz, gin;
    {
        const size_t b0 = (size_t)bg * G3 + ug;
        gir = __ldcg(&g_gi[b0]);
        giz = __ldcg(&g_gi[b0 + DH]);
        gin = __ldcg(&g_gi[b0 + 2 * DH]);
    }

    for (int s = 0; s < SEQ; s++) {
        const int rb = (s - 1) & 1;
        const int wb = s & 1;
        const uint32_t pw = (uint32_t)(((s - 1) >> 1) & 1);

        // prefetch gi(s+1) before any wait
        float girN = 0.f, gizN = 0.f, ginN = 0.f;
        if (s + 1 < SEQ) {
            const size_t b = ((size_t)(s + 1) * BATCH + bg) * G3 + ug;
            girN = __ldcg(&g_gi[b]);
            gizN = __ldcg(&g_gi[b + DH]);
            ginN = __ldcg(&g_gi[b + 2 * DH]);
        }

#pragma unroll
        for (int grp = 0; grp < 2; grp++) {
            // ---- wait + compute (all 256 threads) ----
            const uint32_t mgoff = (uint32_t)(grp * 16 * 8);
            if (s > 0) {
                const uint32_t mymb = mb_local + mgoff + (uint32_t)((sw * 2 + rb) * 8);
                mbar_wait(mymb, pw);
                if (lane == 0 && s + 2 < SEQ)
                    mbar_expect_tx(mymb, SLICE * 4);
            }

            const float* hbc = h_sh + (grp * 2 + rb) * HBUF;
            unsigned long long acc[4][6];
#pragma unroll
            for (int i = 0; i < 4; i++)
#pragma unroll
                for (int j = 0; j < 6; j++) acc[i][j] = 0ull;

#pragma unroll
            for (int q = 0; q < 4; q++) {
                ulonglong2 hq[4];
#pragma unroll
                for (int i = 0; i < 4; i++)
                    hq[i] = *(const ulonglong2*)&hbc[hoff + i * UPB + q * 4];
#pragma unroll
                for (int i = 0; i < 4; i++)
#pragma unroll
                    for (int j = 0; j < 6; j++) {
                        fma2(acc[i][j], hq[i].x, Wr[j][q].x);
                        fma2(acc[i][j], hq[i].y, Wr[j][q].y);
                    }
            }

            float* ppw = part + (grp * 2 + wb) * PARTN;
#pragma unroll
            for (int i = 0; i < 4; i++)
#pragma unroll
                for (int j = 0; j < 6; j++) {
                    float2 f = u2f2(acc[i][j]);
                    float v = f.x + f.y;
                    v += __shfl_xor_sync(0xffffffffu, v, 16);
                    if ((tid & 16) == 0)
                        ppw[(i * ROWSB + rq + 16 * j) * 9 + sw] = v;
                }
            __syncthreads();

            // ---- epilogue for THIS group, on its owning half-block only ----
            if (egrp == grp) {
                const float* pp = part + (grp * 2 + wb) * PARTN;
                const float* hb = h_sh + (grp * 2 + rb) * HBUF;
                const int o_r = (eb * ROWSB + eu) * 9;
                const int o_z = (eb * ROWSB + UPB + eu) * 9;
                const int o_n = (eb * ROWSB + 2 * UPB + eu) * 9;
                float Ar = ((pp[o_r + 0] + pp[o_r + 1]) + (pp[o_r + 2] + pp[o_r + 3])) +
                           ((pp[o_r + 4] + pp[o_r + 5]) + (pp[o_r + 6] + pp[o_r + 7])) +
                           (bhh0 + gir);
                float Az = ((pp[o_z + 0] + pp[o_z + 1]) + (pp[o_z + 2] + pp[o_z + 3])) +
                           ((pp[o_z + 4] + pp[o_z + 5]) + (pp[o_z + 6] + pp[o_z + 7])) +
                           (bhh1 + giz);
                float An = ((pp[o_n + 0] + pp[o_n + 1]) + (pp[o_n + 2] + pp[o_n + 3])) +
                           ((pp[o_n + 4] + pp[o_n + 5]) + (pp[o_n + 6] + pp[o_n + 7])) +
                           bhh2;
                const float rr = fsigmoid(Ar);
                const float zz = fsigmoid(Az);
                const float nn = ftanh_fast(fmaf(rr, An, gin));
                const float hold = hb[ut * SLICE + et];
                const float hnew = fmaf(zz, hold - nn, nn);

                float* sg = stg + (grp * 2 + wb) * SLICE;
                sg[et] = hnew;
                __syncwarp();
                if (eu == 0 && s + 1 < SEQ) {
                    asm volatile("fence.proxy.async.shared::cta;" ::: "memory");
                    const uint32_t src   = stg_local +
                        (uint32_t)(((grp * 2 + wb) * SLICE + eb * 32) * 4);
                    const uint32_t doff  = (uint32_t)((grp * 2 + wb) * HBUF * 4 +
                        ut * SLICE * 4 + eb * 128);
                    const uint32_t mboff = (uint32_t)(grp * 16 * 8 + (ut * 2 + wb) * 8);
#pragma unroll
                    for (int r = 0; r < NP; r++)
                        bulk_push(peer_h[r] + doff, src, 128, peer_mb[r] + mboff);
                }

                g_outs[((size_t)s * BATCH + bg) * DH + ug] = hnew;
                gir = girN; giz = gizN; gin = ginN;   // advance gi pipeline
            }
        }
    }

    CLUSTER_SYNC_();   // nothing in flight targets a peer after this
}

// ---------------- Phase 3: attention ----------------
__global__ void k_scores(const float* __restrict__ watt) {
    __shared__ float wsm[DH];
    const int tid = threadIdx.x;
    wsm[tid] = watt[tid];   // blockDim = 256 = DH
    __syncthreads();
    const int s = blockIdx.x;
    const int w = tid >> 5, l = tid & 31;
#pragma unroll
    for (int bb = w; bb < BATCH; bb += 8) {
        const float* row = &g_outs[((size_t)s * BATCH + bb) * DH];
        float acc = 0.f;
#pragma unroll
        for (int k = l; k < DH; k += 32) acc = fmaf(row[k], wsm[k], acc);
#pragma unroll
        for (int o = 16; o > 0; o >>= 1) acc += __shfl_xor_sync(0xffffffffu, acc, o);
        if (l == 0) g_scores[s * BATCH + bb] = acc;
    }
}

__global__ void k_softmax() {
    __shared__ float red[256];
    const int b = blockIdx.x, tid = threadIdx.x;
    float mx = -1e30f;
    for (int s = tid; s < SEQ; s += 256) mx = fmaxf(mx, g_scores[s * BATCH + b]);
    red[tid] = mx; __syncthreads();
    for (int o = 128; o > 0; o >>= 1) { if (tid < o) red[tid] = fmaxf(red[tid], red[tid + o]); __syncthreads(); }
    mx = red[0]; __syncthreads();
    float sum = 0.f;
    for (int s = tid; s < SEQ; s += 256) sum += __expf(g_scores[s * BATCH + b] - mx);
    red[tid] = sum; __syncthreads();
    for (int o = 128; o > 0; o >>= 1) { if (tid < o) red[tid] += red[tid + o]; __syncthreads(); }
    const float inv = 1.0f / red[0];
    for (int s = tid; s < SEQ; s += 256)
        g_scores[s * BATCH + b] = __expf(g_scores[s * BATCH + b] - mx) * inv;
}

__global__ void k_wsum1() {
    const int b = blockIdx.x, c = blockIdx.y, h = threadIdx.x;
    float acc = 0.f;
    const int s0 = c * 256;
#pragma unroll 4
    for (int s = s0; s < s0 + 256; s++)
        acc = fmaf(__ldg(&g_scores[s * BATCH + b]),
                   g_outs[((size_t)s * BATCH + b) * DH + h], acc);
    g_wpart[(c * BATCH + b) * DH + h] = acc;
}

__global__ void k_wsum2(float* __restrict__ out) {
    const int b = blockIdx.x, h = threadIdx.x;
    float acc = 0.f;
#pragma unroll
    for (int c = 0; c < 8; c++) acc += g_wpart[(c * BATCH + b) * DH + h];
    out[b * DH + h] = acc;
}

// ---------------- launch ----------------
extern "C" void kernel_launch(void* const* d_in, const int* in_sizes, int n_in,
                              void* d_out, int out_size) {
    const float* data = (const float*)d_in[0];
    const float* Wih  = (const float*)d_in[1];
    const float* Whh  = (const float*)d_in[2];
    const float* bih  = (const float*)d_in[3];
    const float* bhh  = (const float*)d_in[4];
    const float* watt = (const float*)d_in[5];
    float* out = (float*)d_out;

    const int gi_smem  = 2 * 128 * 132 * (int)sizeof(float);                      // 135168
    const int gru_smem = (4 * HBUF + 4 * SLICE + 4 * PARTN) * (int)sizeof(float); // 73728

    cudaFuncSetAttribute(gi_gemm, cudaFuncAttributeMaxDynamicSharedMemorySize, gi_smem);
    cudaFuncSetAttribute(gru_rec, cudaFuncAttributeMaxDynamicSharedMemorySize, gru_smem);

    dim3 gg(G3 / 128, (SEQ * BATCH) / 128);   // (6, 1024)
    gi_gemm<<<gg, 256, gi_smem>>>(data, Wih, bih);
    k_nop<<<1, 32>>>();                        // launch-slot shims: make gru_rec
    k_nop<<<1, 32>>>();                        // the 4th launch (= ncu capture slot)
    gru_rec<<<NCL * NP, 256, gru_smem>>>(Whh, bhh);
    k_scores<<<SEQ, 256>>>(watt);
    k_softmax<<<BATCH, 256>>>();
    dim3 gw(BATCH, 8);
    k_wsum1<<<gw, 256>>>();
    k_wsum2<<<BATCH, 256>>>(out);
}